// round 15
// baseline (speedup 1.0000x reference)
#include <cuda_runtime.h>
#include <cuda_bf16.h>
#include <cstdint>

// Warp-specialized Affine_Linear (HMMA; tcgen05 unavailable on compute_103 target).
// Round-14 base (63.9us) minus the whole output-staging pipeline:
// consumers STG accumulators directly to Y (L2 merges sectors), arrive EMPTY
// right after the k-loop; producers drop y_copy/bar10/drain.
//  barriers: 1..6 = FULLsub(buf,mtile) cnt384 ; 7,8 = EMPTY(buf) cnt512

#define THREADS 512
#define NPROD   320
#define NCONS   192
#define TOKBUF  32
#define NITEMS  (TOKBUF*32)
#define APITCH  392            // halves/row (784B = 49 chunks == 1 mod 8, ldsm conflict-free)
#define BPITCH  72             // halves/row (144B = 9 chunks == 1 mod 8)
#define SB_BYTES   (384*BPITCH*2)            // 55296
#define ABUF_BYTES (96*APITCH*2)             // 75264
#define SMEM_TOTAL (SB_BYTES + 2*ABUF_BYTES) // 205824

__device__ __forceinline__ uint32_t smem_u32(const void* p) {
    return (uint32_t)__cvta_generic_to_shared(p);
}
__device__ __forceinline__ void ldsm_x4(uint32_t* r, uint32_t addr) {
    asm volatile("ldmatrix.sync.aligned.m8n8.x4.shared.b16 {%0,%1,%2,%3}, [%4];"
                 : "=r"(r[0]), "=r"(r[1]), "=r"(r[2]), "=r"(r[3]) : "r"(addr));
}
__device__ __forceinline__ void ldsm_x4_t(uint32_t* r, uint32_t addr) {
    asm volatile("ldmatrix.sync.aligned.m8n8.x4.trans.shared.b16 {%0,%1,%2,%3}, [%4];"
                 : "=r"(r[0]), "=r"(r[1]), "=r"(r[2]), "=r"(r[3]) : "r"(addr));
}
__device__ __forceinline__ void mma16816(float* c, const uint32_t* a, uint32_t b0, uint32_t b1) {
    asm volatile("mma.sync.aligned.m16n8k16.row.col.f32.bf16.bf16.f32 "
                 "{%0,%1,%2,%3}, {%4,%5,%6,%7}, {%8,%9}, {%0,%1,%2,%3};"
                 : "+f"(c[0]), "+f"(c[1]), "+f"(c[2]), "+f"(c[3])
                 : "r"(a[0]), "r"(a[1]), "r"(a[2]), "r"(a[3]), "r"(b0), "r"(b1));
}
__device__ __forceinline__ void prefetch_l2(const void* p) {
    asm volatile("prefetch.global.L2 [%0];" :: "l"(p));
}

struct Frag {
    uint32_t ah0[4], ah1[4], al0[4], al1[4];
    uint32_t bh[2][4], bl[2][4];
};

__device__ __forceinline__ void load_frags(Frag& F, uint32_t aBase, uint32_t bBase, int ks) {
    uint32_t ao = (uint32_t)(ks * 32);
    ldsm_x4(F.ah0, aBase + ao);
    ldsm_x4(F.ah1, aBase + 16 * APITCH * 2 + ao);
    ldsm_x4(F.al0, aBase + 384 + ao);
    ldsm_x4(F.al1, aBase + 16 * APITCH * 2 + 384 + ao);
    uint32_t bo = (uint32_t)(ks * 16 * BPITCH * 2);
    ldsm_x4_t(F.bh[0], bBase + bo);
    ldsm_x4_t(F.bh[1], bBase + bo + 32);
    ldsm_x4_t(F.bl[0], bBase + bo + 192 * BPITCH * 2);
    ldsm_x4_t(F.bl[1], bBase + bo + 192 * BPITCH * 2 + 32);
}

// three sweeps of 8 -> 7 independent MMAs between dependent acc updates
__device__ __forceinline__ void do_mmas(float acc[2][4][4], const Frag& F) {
#pragma unroll
    for (int q = 0; q < 2; q++)
#pragma unroll
        for (int j = 0; j < 2; j++) {
            mma16816(acc[0][2*q+j], F.ah0, F.bh[q][2*j], F.bh[q][2*j+1]);
            mma16816(acc[1][2*q+j], F.ah1, F.bh[q][2*j], F.bh[q][2*j+1]);
        }
#pragma unroll
    for (int q = 0; q < 2; q++)
#pragma unroll
        for (int j = 0; j < 2; j++) {
            mma16816(acc[0][2*q+j], F.al0, F.bh[q][2*j], F.bh[q][2*j+1]);
            mma16816(acc[1][2*q+j], F.al1, F.bh[q][2*j], F.bh[q][2*j+1]);
        }
#pragma unroll
    for (int q = 0; q < 2; q++)
#pragma unroll
        for (int j = 0; j < 2; j++) {
            mma16816(acc[0][2*q+j], F.ah0, F.bl[q][2*j], F.bl[q][2*j+1]);
            mma16816(acc[1][2*q+j], F.ah1, F.bl[q][2*j], F.bl[q][2*j+1]);
        }
}

__device__ __forceinline__ void split2p(__nv_bfloat16* hi, __nv_bfloat16* lo, float v0, float v1) {
    __nv_bfloat16 h0 = __float2bfloat16(v0);
    __nv_bfloat16 h1 = __float2bfloat16(v1);
    *(__nv_bfloat162*)hi = __halves2bfloat162(h0, h1);
    *(__nv_bfloat162*)lo = __halves2bfloat162(__float2bfloat16(v0 - __bfloat162float(h0)),
                                              __float2bfloat16(v1 - __bfloat162float(h1)));
}

__device__ __forceinline__ void frame_terms(float a1x, float a2x, float a1y, float a2y,
                                            float a1z, float a2z,
                                            float x0, float x1, float x2, float t[3][3]) {
    float s1   = fmaf(a1x, a1x, fmaf(a1y, a1y, a1z * a1z));
    float inv1 = rsqrtf(fmaxf(s1, 1e-24f));
    float b1x = a1x * inv1, b1y = a1y * inv1, b1z = a1z * inv1;

    float d  = fmaf(b1x, a2x, fmaf(b1y, a2y, b1z * a2z));
    float ux = fmaf(-d, b1x, a2x);
    float uy = fmaf(-d, b1y, a2y);
    float uz = fmaf(-d, b1z, a2z);
    float s2   = fmaf(ux, ux, fmaf(uy, uy, uz * uz));
    float inv2 = rsqrtf(fmaxf(s2, 1e-24f));
    float b2x = ux * inv2, b2y = uy * inv2, b2z = uz * inv2;

    float b3x = fmaf(b1y, b2z, -b1z * b2y);
    float b3y = fmaf(b1z, b2x, -b1x * b2z);
    float b3z = fmaf(b1x, b2y, -b1y * b2x);

    float rt0 = fmaf(b1x, x0, fmaf(b1y, x1, b1z * x2));
    float rt1 = fmaf(b2x, x0, fmaf(b2y, x1, b2z * x2));
    float rt2 = fmaf(b3x, x0, fmaf(b3y, x1, b3z * x2));

    t[0][0] = fmaf(b1x, rt0,  b2x * rt1);
    t[0][1] = fmaf(b1y, rt0,  b2y * rt1);
    t[0][2] = fmaf(b1z, rt0,  b2z * rt1);
    t[1][0] = fmaf(b2x, rt0, -b1x * rt1);
    t[1][1] = fmaf(b2y, rt0, -b1y * rt1);
    t[1][2] = fmaf(b2z, rt0, -b1z * rt1);
    t[2][0] = b3x * rt2;
    t[2][1] = b3y * rt2;
    t[2][2] = b3z * rt2;
}

struct Stage {
    float4 j0, j1, j2;
    float2 xa, xb, xc;
};

__device__ __forceinline__ Stage load_stage(const float* __restrict__ X,
                                            const float* __restrict__ J,
                                            long long tokBase, int p) {
    Stage s;
    int tok = p >> 5;
    int e0  = (p & 31) << 1;
    long long base = (tokBase + tok) * 64 + e0;
    const float4* Jp = (const float4*)(J + base * 6);
    s.j0 = Jp[0]; s.j1 = Jp[1]; s.j2 = Jp[2];
    const float2* Xp = (const float2*)(X + base * 3);
    s.xa = Xp[0]; s.xb = Xp[1]; s.xc = Xp[2];
    return s;
}

__device__ __forceinline__ void pf_item(const float* __restrict__ X,
                                        const float* __restrict__ J,
                                        long long tokBaseN, int p) {
    int tok = p >> 5;
    int e0  = (p & 31) << 1;
    long long base = (tokBaseN + tok) * 64 + e0;
    prefetch_l2(J + base * 6);
    prefetch_l2(X + base * 3);
}

__device__ __forceinline__ void compute_store(const Stage& s, int p, __nv_bfloat16* sA) {
    int tok = p >> 5;
    int e0  = (p & 31) << 1;
    float t0[3][3], t1[3][3];
    frame_terms(s.j0.x, s.j0.y, s.j0.z, s.j0.w, s.j1.x, s.j1.y,
                s.xa.x, s.xa.y, s.xb.x, t0);
    frame_terms(s.j1.z, s.j1.w, s.j2.x, s.j2.y, s.j2.z, s.j2.w,
                s.xb.y, s.xc.x, s.xc.y, t1);
    int k0 = 3 * e0;
#pragma unroll
    for (int i = 0; i < 3; i++) {
        __nv_bfloat16* r = sA + (tok * 3 + i) * APITCH + k0;
        split2p(r + 0, r + 192 + 0, t0[0][i], t0[1][i]);
        split2p(r + 2, r + 192 + 2, t0[2][i], t1[0][i]);
        split2p(r + 4, r + 192 + 4, t1[1][i], t1[2][i]);
    }
}

__global__ __launch_bounds__(THREADS, 1)
void affine_ws10(const float* __restrict__ X,
                 const float* __restrict__ J,
                 const float* __restrict__ A,
                 const float* __restrict__ Bm,
                 const float* __restrict__ C,
                 float* __restrict__ Y,
                 int ngroups)
{
    extern __shared__ char smem[];
    __nv_bfloat16* sB  = (__nv_bfloat16*)smem;               // [k(384)][f(64)] pitch BPITCH
    __nv_bfloat16* sA0 = (__nv_bfloat16*)(smem + SB_BYTES);  // two buffers [96][APITCH]

    const int tid = threadIdx.x;

    // ---- weights -> sB, split hi/lo, packed bf16x2 along f ----
    for (int q = tid; q < 2048; q += THREADS) {
        int e  = q & 63;
        int f0 = (q >> 6) << 1;
        float wa0 = A[f0 * 64 + e],  wa1 = A[(f0 + 1) * 64 + e];
        float wb0 = Bm[f0 * 64 + e], wb1 = Bm[(f0 + 1) * 64 + e];
        float wc0 = C[f0 * 64 + e],  wc1 = C[(f0 + 1) * 64 + e];
        int k = e * 3;
        split2p(&sB[(k+0)*BPITCH + f0], &sB[(192+k+0)*BPITCH + f0], wa0, wa1);
        split2p(&sB[(k+1)*BPITCH + f0], &sB[(192+k+1)*BPITCH + f0], wb0, wb1);
        split2p(&sB[(k+2)*BPITCH + f0], &sB[(192+k+2)*BPITCH + f0], wc0, wc1);
    }
    __syncthreads();

    if (tid < NPROD) {
        // ================= PRODUCERS (warps 0-9) =================
        int it = 0;
        for (int g = blockIdx.x; g < ngroups; g += gridDim.x, it++) {
            int buf = it & 1;
            __nv_bfloat16* sA = sA0 + buf * (ABUF_BYTES / 2);
            long long tokBase = (long long)g * TOKBUF;

            // prefetch the first item BEFORE blocking on the EMPTY barrier
            Stage s0 = load_stage(X, J, tokBase, tid);

            if (it >= 2) {
                int bid = 7 + buf;   // EMPTY: consumers finished reading sA (it-2)
                asm volatile("bar.sync %0, %1;" :: "r"(bid), "n"(THREADS) : "memory");
            }

            const int gn = g + gridDim.x;
            const bool pf = (gn < ngroups);
            const long long tokBaseN = (long long)gn * TOKBUF;
            const int fb = 1 + buf * 3;   // FULLsub barrier base id
            const bool has3 = (tid + 3 * NPROD) < NITEMS;   // tid < 64

            // explicitly unrolled, 1-deep pipelined item sequence (max 2 stages live)
            Stage s1 = load_stage(X, J, tokBase, tid + NPROD);
            if (pf) pf_item(X, J, tokBaseN, tid);
            compute_store(s0, tid, sA);                       // item 0 (toks 0-9)

            Stage s2 = load_stage(X, J, tokBase, tid + 2 * NPROD);
            if (pf) pf_item(X, J, tokBaseN, tid + NPROD);
            compute_store(s1, tid + NPROD, sA);               // item 1 (toks 10-19)
            asm volatile("bar.arrive %0, %1;" :: "r"(fb), "n"(384) : "memory");     // FULL m-tile 0

            Stage s3;
            if (has3) s3 = load_stage(X, J, tokBase, tid + 3 * NPROD);
            if (pf) pf_item(X, J, tokBaseN, tid + 2 * NPROD);
            compute_store(s2, tid + 2 * NPROD, sA);           // item 2 (toks 20-29)
            asm volatile("bar.arrive %0, %1;" :: "r"(fb + 1), "n"(384) : "memory"); // FULL m-tile 1

            if (has3) {
                if (pf) pf_item(X, J, tokBaseN, tid + 3 * NPROD);
                compute_store(s3, tid + 3 * NPROD, sA);       // item 3 (toks 30-31)
            }
            asm volatile("bar.arrive %0, %1;" :: "r"(fb + 2), "n"(384) : "memory"); // FULL m-tile 2
        }
    } else {
        // ================= CONSUMERS (warps 10-15) =================
        const int cw   = (tid - NPROD) >> 5;   // 0..5
        const int lane = tid & 31;
        const int mt0  = cw >> 1;              // m-tile index 0..2
        const int row0 = mt0 * 32;
        const int n0   = (cw & 1) * 32;
        const int gq   = lane >> 2;
        const int tq   = lane & 3;

        // loop-invariant Y-linear offsets for the 4 row variants (mt,half)
        int offY[4];
#pragma unroll
        for (int v = 0; v < 4; v++) {
            int r   = row0 + (v >> 1) * 16 + (v & 1) * 8 + gq;
            int tok = r / 3;
            offY[v] = tok * 192 + (r - 3 * tok);
        }

        const uint32_t bBase = smem_u32(sB + (lane & 15) * BPITCH + n0 + ((lane >> 4) << 3));

        int it = 0;
        for (int g = blockIdx.x; g < ngroups; g += gridDim.x, it++) {
            int buf = it & 1;
            {
                int bid = 1 + buf * 3 + mt0;   // FULLsub for this m-tile
                asm volatile("bar.sync %0, %1;" :: "r"(bid), "n"(384) : "memory");
            }
            __nv_bfloat16* sA = sA0 + buf * (ABUF_BYTES / 2);

            uint32_t aBase = smem_u32(sA + (row0 + (lane & 15)) * APITCH + ((lane >> 4) << 3));

            float acc[2][4][4];
#pragma unroll
            for (int mt = 0; mt < 2; mt++)
#pragma unroll
                for (int q = 0; q < 4; q++)
#pragma unroll
                    for (int r = 0; r < 4; r++) acc[mt][q][r] = 0.f;

            // software-pipelined k-loop (12 steps, double-buffered fragments)
            Frag F[2];
            load_frags(F[0], aBase, bBase, 0);
#pragma unroll
            for (int ks = 0; ks < 12; ks++) {
                if (ks < 11) load_frags(F[(ks + 1) & 1], aBase, bBase, ks + 1);
                do_mmas(acc, F[ks & 1]);
            }

            // sA fully read (register deps on ldsm results) -> release immediately
            {
                int bid = 7 + buf;   // EMPTY
                asm volatile("bar.arrive %0, %1;" :: "r"(bid), "n"(THREADS) : "memory");
            }

            // direct STG epilogue: scattered 4B stores, merged in L2
            float* Yg = Y + (long long)g * (TOKBUF * 192);
#pragma unroll
            for (int mt = 0; mt < 2; mt++) {
#pragma unroll
                for (int q = 0; q < 4; q++) {
                    int col3 = (n0 + q * 8 + tq * 2) * 3;
                    Yg[offY[mt*2+0] + col3]     = acc[mt][q][0];
                    Yg[offY[mt*2+0] + col3 + 3] = acc[mt][q][1];
                    Yg[offY[mt*2+1] + col3]     = acc[mt][q][2];
                    Yg[offY[mt*2+1] + col3 + 3] = acc[mt][q][3];
                }
            }
        }
    }
}

extern "C" void kernel_launch(void* const* d_in, const int* in_sizes, int n_in,
                              void* d_out, int out_size)
{
    const float* X  = (const float*)d_in[0];
    const float* J  = (const float*)d_in[1];
    const float* A  = (const float*)d_in[2];
    const float* Bm = (const float*)d_in[3];
    const float* C  = (const float*)d_in[4];
    float* Y = (float*)d_out;

    int ntok    = in_sizes[0] / (64 * 3);   // B*N
    int ngroups = ntok / TOKBUF;            // 2048

    cudaFuncSetAttribute(affine_ws10,
                         cudaFuncAttributeMaxDynamicSharedMemorySize, SMEM_TOTAL);

    int blocks = 152;
    if (blocks > ngroups) blocks = ngroups;
    affine_ws10<<<blocks, THREADS, SMEM_TOTAL>>>(X, J, A, Bm, C, Y, ngroups);
}

// round 16
// speedup vs baseline: 1.0372x; 1.0372x over previous
#include <cuda_runtime.h>
#include <cuda_bf16.h>
#include <cstdint>

// Warp-specialized Affine_Linear (HMMA; tcgen05 unavailable on compute_103 target).
// TWO independent pipelines per CTA, interleaved groups of 16 tokens each:
//   P0: producer warps 0-4, consumer warps 5-7   (buffers 0,1)
//   P1: consumer warps 8-10, producer warps 11-15 (buffers 2,3)
// Desynchronized phases: one pipeline's warps issue while the other stalls.
//  barriers: P0 FULL=1+buf EMPTY=3+buf ; P1 FULL=5+buf EMPTY=7+buf (all cnt 256)

#define THREADS 512
#define PPROD   160            // 5 producer warps per pipeline
#define PCONS   96             // 3 consumer warps per pipeline
#define TOKBUF  16
#define NITEMS  (TOKBUF*32)    // 512 e-pair items per group
#define APITCH  392            // halves/row (784B = 49 chunks == 1 mod 8, ldsm conflict-free)
#define BPITCH  72             // halves/row (144B = 9 chunks == 1 mod 8)
#define SB_BYTES (384*BPITCH*2)              // 55296
#define ABUF     (48*APITCH*2)               // 37632 per buffer (48 rows)
#define SMEM_TOTAL (SB_BYTES + 4*ABUF)       // 205824

__device__ __forceinline__ uint32_t smem_u32(const void* p) {
    return (uint32_t)__cvta_generic_to_shared(p);
}
__device__ __forceinline__ void ldsm_x4(uint32_t* r, uint32_t addr) {
    asm volatile("ldmatrix.sync.aligned.m8n8.x4.shared.b16 {%0,%1,%2,%3}, [%4];"
                 : "=r"(r[0]), "=r"(r[1]), "=r"(r[2]), "=r"(r[3]) : "r"(addr));
}
__device__ __forceinline__ void ldsm_x4_t(uint32_t* r, uint32_t addr) {
    asm volatile("ldmatrix.sync.aligned.m8n8.x4.trans.shared.b16 {%0,%1,%2,%3}, [%4];"
                 : "=r"(r[0]), "=r"(r[1]), "=r"(r[2]), "=r"(r[3]) : "r"(addr));
}
__device__ __forceinline__ void mma16816(float* c, const uint32_t* a, uint32_t b0, uint32_t b1) {
    asm volatile("mma.sync.aligned.m16n8k16.row.col.f32.bf16.bf16.f32 "
                 "{%0,%1,%2,%3}, {%4,%5,%6,%7}, {%8,%9}, {%0,%1,%2,%3};"
                 : "+f"(c[0]), "+f"(c[1]), "+f"(c[2]), "+f"(c[3])
                 : "r"(a[0]), "r"(a[1]), "r"(a[2]), "r"(a[3]), "r"(b0), "r"(b1));
}
__device__ __forceinline__ void prefetch_l2(const void* p) {
    asm volatile("prefetch.global.L2 [%0];" :: "l"(p));
}

__device__ __forceinline__ void split2p(__nv_bfloat16* hi, __nv_bfloat16* lo, float v0, float v1) {
    __nv_bfloat16 h0 = __float2bfloat16(v0);
    __nv_bfloat16 h1 = __float2bfloat16(v1);
    *(__nv_bfloat162*)hi = __halves2bfloat162(h0, h1);
    *(__nv_bfloat162*)lo = __halves2bfloat162(__float2bfloat16(v0 - __bfloat162float(h0)),
                                              __float2bfloat16(v1 - __bfloat162float(h1)));
}

__device__ __forceinline__ void frame_terms(float a1x, float a2x, float a1y, float a2y,
                                            float a1z, float a2z,
                                            float x0, float x1, float x2, float t[3][3]) {
    float s1   = fmaf(a1x, a1x, fmaf(a1y, a1y, a1z * a1z));
    float inv1 = rsqrtf(fmaxf(s1, 1e-24f));
    float b1x = a1x * inv1, b1y = a1y * inv1, b1z = a1z * inv1;

    float d  = fmaf(b1x, a2x, fmaf(b1y, a2y, b1z * a2z));
    float ux = fmaf(-d, b1x, a2x);
    float uy = fmaf(-d, b1y, a2y);
    float uz = fmaf(-d, b1z, a2z);
    float s2   = fmaf(ux, ux, fmaf(uy, uy, uz * uz));
    float inv2 = rsqrtf(fmaxf(s2, 1e-24f));
    float b2x = ux * inv2, b2y = uy * inv2, b2z = uz * inv2;

    float b3x = fmaf(b1y, b2z, -b1z * b2y);
    float b3y = fmaf(b1z, b2x, -b1x * b2z);
    float b3z = fmaf(b1x, b2y, -b1y * b2x);

    float rt0 = fmaf(b1x, x0, fmaf(b1y, x1, b1z * x2));
    float rt1 = fmaf(b2x, x0, fmaf(b2y, x1, b2z * x2));
    float rt2 = fmaf(b3x, x0, fmaf(b3y, x1, b3z * x2));

    t[0][0] = fmaf(b1x, rt0,  b2x * rt1);
    t[0][1] = fmaf(b1y, rt0,  b2y * rt1);
    t[0][2] = fmaf(b1z, rt0,  b2z * rt1);
    t[1][0] = fmaf(b2x, rt0, -b1x * rt1);
    t[1][1] = fmaf(b2y, rt0, -b1y * rt1);
    t[1][2] = fmaf(b2z, rt0, -b1z * rt1);
    t[2][0] = b3x * rt2;
    t[2][1] = b3y * rt2;
    t[2][2] = b3z * rt2;
}

struct Stage {
    float4 j0, j1, j2;
    float2 xa, xb, xc;
};

__device__ __forceinline__ Stage load_stage(const float* __restrict__ X,
                                            const float* __restrict__ J,
                                            long long tokBase, int p) {
    Stage s;
    int tok = p >> 5;
    int e0  = (p & 31) << 1;
    long long base = (tokBase + tok) * 64 + e0;
    const float4* Jp = (const float4*)(J + base * 6);
    s.j0 = Jp[0]; s.j1 = Jp[1]; s.j2 = Jp[2];
    const float2* Xp = (const float2*)(X + base * 3);
    s.xa = Xp[0]; s.xb = Xp[1]; s.xc = Xp[2];
    return s;
}

__device__ __forceinline__ void pf_item(const float* __restrict__ X,
                                        const float* __restrict__ J,
                                        long long tokBaseN, int p) {
    int tok = p >> 5;
    int e0  = (p & 31) << 1;
    long long base = (tokBaseN + tok) * 64 + e0;
    prefetch_l2(J + base * 6);
    prefetch_l2(X + base * 3);
}

__device__ __forceinline__ void compute_store(const Stage& s, int p, __nv_bfloat16* sA) {
    int tok = p >> 5;
    int e0  = (p & 31) << 1;
    float t0[3][3], t1[3][3];
    frame_terms(s.j0.x, s.j0.y, s.j0.z, s.j0.w, s.j1.x, s.j1.y,
                s.xa.x, s.xa.y, s.xb.x, t0);
    frame_terms(s.j1.z, s.j1.w, s.j2.x, s.j2.y, s.j2.z, s.j2.w,
                s.xb.y, s.xc.x, s.xc.y, t1);
    int k0 = 3 * e0;
#pragma unroll
    for (int i = 0; i < 3; i++) {
        __nv_bfloat16* r = sA + (tok * 3 + i) * APITCH + k0;
        split2p(r + 0, r + 192 + 0, t0[0][i], t0[1][i]);
        split2p(r + 2, r + 192 + 2, t0[2][i], t1[0][i]);
        split2p(r + 4, r + 192 + 4, t1[1][i], t1[2][i]);
    }
}

// ---------------- producer role (one pipeline) ----------------
__device__ __forceinline__ void run_producer(const float* __restrict__ X,
                                             const float* __restrict__ J,
                                             __nv_bfloat16* bufBase,  // 2 buffers
                                             int ptid, int pipe, int ngroups, int gridX,
                                             int bFULL, int bEMPTY)
{
    int it = 0;
    for (int g = blockIdx.x + pipe * gridX; g < ngroups; g += 2 * gridX, it++) {
        int buf = it & 1;
        __nv_bfloat16* sA = bufBase + buf * (ABUF / 2);
        long long tokBase = (long long)g * TOKBUF;

        // first item's loads issue BEFORE blocking on EMPTY
        Stage cur = load_stage(X, J, tokBase, ptid);

        if (it >= 2) {
            int bid = bEMPTY + buf;
            asm volatile("bar.sync %0, %1;" :: "r"(bid), "n"(256) : "memory");
        }

        const int gn = g + 2 * gridX;
        const bool pf = (gn < ngroups);
        const long long tokBaseN = (long long)gn * TOKBUF;

        int p = ptid;
#pragma unroll 1
        while (p < NITEMS) {
            int pn = p + PPROD;
            Stage nxt;
            if (pn < NITEMS) nxt = load_stage(X, J, tokBase, pn);
            if (pf) pf_item(X, J, tokBaseN, p);
            compute_store(cur, p, sA);
            cur = nxt;
            p = pn;
        }
        {
            int bid = bFULL + buf;
            asm volatile("bar.arrive %0, %1;" :: "r"(bid), "n"(256) : "memory");
        }
    }
}

// ---------------- consumer role (one pipeline) ----------------
__device__ __forceinline__ void run_consumer(float* __restrict__ Y,
                                             const __nv_bfloat16* sB,
                                             __nv_bfloat16* bufBase,
                                             int ctid, int pipe, int ngroups, int gridX,
                                             int bFULL, int bEMPTY)
{
    const int cw   = ctid >> 5;        // 0..2 -> m-tile (16 rows each)
    const int lane = ctid & 31;
    const int row0 = cw * 16;
    const int gq   = lane >> 2;
    const int tq   = lane & 3;

    // Y-linear offsets for the 2 row variants of m16n8 fragments
    int offY[2];
#pragma unroll
    for (int v = 0; v < 2; v++) {
        int r   = row0 + v * 8 + gq;
        int tok = r / 3;
        offY[v] = tok * 192 + (r - 3 * tok);
    }

    const uint32_t bBase = smem_u32(sB + (lane & 15) * BPITCH + ((lane >> 4) << 3));

    int it = 0;
    for (int g = blockIdx.x + pipe * gridX; g < ngroups; g += 2 * gridX, it++) {
        int buf = it & 1;
        {
            int bid = bFULL + buf;
            asm volatile("bar.sync %0, %1;" :: "r"(bid), "n"(256) : "memory");
        }
        __nv_bfloat16* sA = bufBase + buf * (ABUF / 2);
        uint32_t aBase = smem_u32(sA + (row0 + (lane & 15)) * APITCH + ((lane >> 4) << 3));

        float acc[8][4];
#pragma unroll
        for (int q = 0; q < 8; q++)
#pragma unroll
            for (int r = 0; r < 4; r++) acc[q][r] = 0.f;

        // k-loop: m16 x n64, fused bf16x3 split; cross-pipeline warps hide ldsm latency
#pragma unroll 2
        for (int ks = 0; ks < 12; ks++) {
            uint32_t ao = (uint32_t)(ks * 32);
            uint32_t ah[4], al[4];
            ldsm_x4(ah, aBase + ao);
            ldsm_x4(al, aBase + 384 + ao);
            uint32_t bo = (uint32_t)(ks * 16 * BPITCH * 2);
            uint32_t bh[4][4], bl[4][4];
#pragma unroll
            for (int j = 0; j < 4; j++) {
                ldsm_x4_t(bh[j], bBase + bo + j * 32);
                ldsm_x4_t(bl[j], bBase + bo + 192 * BPITCH * 2 + j * 32);
            }
            // 3 sweeps of 8 independent MMAs
#pragma unroll
            for (int q = 0; q < 8; q++)
                mma16816(acc[q], ah, bh[q >> 1][2 * (q & 1)], bh[q >> 1][2 * (q & 1) + 1]);
#pragma unroll
            for (int q = 0; q < 8; q++)
                mma16816(acc[q], al, bh[q >> 1][2 * (q & 1)], bh[q >> 1][2 * (q & 1) + 1]);
#pragma unroll
            for (int q = 0; q < 8; q++)
                mma16816(acc[q], ah, bl[q >> 1][2 * (q & 1)], bl[q >> 1][2 * (q & 1) + 1]);
        }

        // sA fully consumed into registers -> release
        {
            int bid = bEMPTY + buf;
            asm volatile("bar.arrive %0, %1;" :: "r"(bid), "n"(256) : "memory");
        }

        // direct STG epilogue (scattered 4B stores, merged in L2)
        float* Yg = Y + (long long)g * (TOKBUF * 192);
#pragma unroll
        for (int q = 0; q < 8; q++) {
            int col3 = (q * 8 + tq * 2) * 3;
            Yg[offY[0] + col3]     = acc[q][0];
            Yg[offY[0] + col3 + 3] = acc[q][1];
            Yg[offY[1] + col3]     = acc[q][2];
            Yg[offY[1] + col3 + 3] = acc[q][3];
        }
    }
}

__global__ __launch_bounds__(THREADS, 1)
void affine_dual(const float* __restrict__ X,
                 const float* __restrict__ J,
                 const float* __restrict__ A,
                 const float* __restrict__ Bm,
                 const float* __restrict__ C,
                 float* __restrict__ Y,
                 int ngroups)
{
    extern __shared__ char smem[];
    __nv_bfloat16* sB  = (__nv_bfloat16*)smem;               // [k(384)][f(64)] pitch BPITCH
    __nv_bfloat16* sA0 = (__nv_bfloat16*)(smem + SB_BYTES);  // 4 buffers of 48 rows

    const int tid = threadIdx.x;

    // ---- weights -> sB, split hi/lo, packed bf16x2 along f ----
    for (int q = tid; q < 2048; q += THREADS) {
        int e  = q & 63;
        int f0 = (q >> 6) << 1;
        float wa0 = A[f0 * 64 + e],  wa1 = A[(f0 + 1) * 64 + e];
        float wb0 = Bm[f0 * 64 + e], wb1 = Bm[(f0 + 1) * 64 + e];
        float wc0 = C[f0 * 64 + e],  wc1 = C[(f0 + 1) * 64 + e];
        int k = e * 3;
        split2p(&sB[(k+0)*BPITCH + f0], &sB[(192+k+0)*BPITCH + f0], wa0, wa1);
        split2p(&sB[(k+1)*BPITCH + f0], &sB[(192+k+1)*BPITCH + f0], wb0, wb1);
        split2p(&sB[(k+2)*BPITCH + f0], &sB[(192+k+2)*BPITCH + f0], wc0, wc1);
    }
    __syncthreads();

    const int gridX = gridDim.x;

    if (tid < 160) {
        // P0 producers (warps 0-4)
        run_producer(X, J, sA0, tid, 0, ngroups, gridX, /*FULL*/1, /*EMPTY*/3);
    } else if (tid < 256) {
        // P0 consumers (warps 5-7; SMSP 1,2,3)
        run_consumer(Y, sB, sA0, tid - 160, 0, ngroups, gridX, 1, 3);
    } else if (tid < 352) {
        // P1 consumers (warps 8-10; SMSP 0,1,2)
        run_consumer(Y, sB, sA0 + 2 * (ABUF / 2), tid - 256, 1, ngroups, gridX, 5, 7);
    } else {
        // P1 producers (warps 11-15)
        run_producer(X, J, sA0 + 2 * (ABUF / 2), tid - 352, 1, ngroups, gridX, 5, 7);
    }
}

extern "C" void kernel_launch(void* const* d_in, const int* in_sizes, int n_in,
                              void* d_out, int out_size)
{
    const float* X  = (const float*)d_in[0];
    const float* J  = (const float*)d_in[1];
    const float* A  = (const float*)d_in[2];
    const float* Bm = (const float*)d_in[3];
    const float* C  = (const float*)d_in[4];
    float* Y = (float*)d_out;

    int ntok    = in_sizes[0] / (64 * 3);   // B*N
    int ngroups = ntok / TOKBUF;            // 4096

    cudaFuncSetAttribute(affine_dual,
                         cudaFuncAttributeMaxDynamicSharedMemorySize, SMEM_TOTAL);

    int blocks = 152;
    affine_dual<<<blocks, THREADS, SMEM_TOTAL>>>(X, J, A, Bm, C, Y, ngroups);
}